// round 2
// baseline (speedup 1.0000x reference)
#include <cuda_runtime.h>

#define BB 1024
#define DD 128
#define TT 256
#define HH 64
#define GG 256  // 4*H

// 256 MB scratch for xp0 = xt @ w_ih0^T + (b_ih0 + b_hh0), layout [B][T][4H]
__device__ float g_xp0[(size_t)BB * TT * GG];

// ---------------------------------------------------------------------------
// Fast-but-accurate activations (MUFU.EX2 / MUFU.RCP based, ~2 ulp)
// ---------------------------------------------------------------------------
__device__ __forceinline__ float sigm(float x) {
    // 1/(1+e^-x); x<<0: expf->inf, rcp(inf)=0 OK; x>>0: expf->0 -> 1 OK
    return __fdividef(1.0f, 1.0f + __expf(-x));
}
__device__ __forceinline__ float tanh_acc(float x) {
    float a = fabsf(x);
    float e = __expf(-2.0f * a);           // in (0, 1]
    float r = (1.0f - e) * __fdividef(1.0f, 1.0f + e);
    return copysignf(r, x);
}

// ---------------------------------------------------------------------------
// Kernel 1: xp0[b, t, g] = sum_d x[b, d, t] * w_ih0[g, d] + (b_ih0+b_hh0)[g]
// Grid: 4096 CTAs (b in [0,1024), t-tile of 64). Block: 256 threads.
// smem: wt[128][260] (transposed W, padded) + xs[128][64]  = 165888 B
// Each thread computes an 8(t) x 8(g) register tile, K = 128.
// ---------------------------------------------------------------------------
__global__ __launch_bounds__(256) void k_inproj(
    const float* __restrict__ x,
    const float* __restrict__ w_ih0,
    const float* __restrict__ b_ih0,
    const float* __restrict__ b_hh0)
{
    extern __shared__ float sm[];
    float* wt = sm;              // [128][260]
    float* xs = sm + 128 * 260;  // [128][64]

    const int tid = threadIdx.x;
    const int b   = blockIdx.x >> 2;
    const int t0  = (blockIdx.x & 3) * 64;

    // Load w_ih0 [256][128] -> wt[d][g] (transposed, pad 260 keeps 16B align)
    {
        const float4* w4 = (const float4*)w_ih0;  // 8192 float4s
        #pragma unroll
        for (int i = 0; i < 32; i++) {
            int j  = tid + i * 256;
            int g  = j >> 5;       // row of w_ih0
            int dq = j & 31;       // which float4 along d
            float4 v = w4[j];
            wt[(4 * dq + 0) * 260 + g] = v.x;
            wt[(4 * dq + 1) * 260 + g] = v.y;
            wt[(4 * dq + 2) * 260 + g] = v.z;
            wt[(4 * dq + 3) * 260 + g] = v.w;
        }
    }
    // Load x tile: xs[d][t] = x[b, d, t0+t]  (coalesced over t)
    {
        const float* xb = x + (size_t)b * DD * TT + t0;
        int t = tid & 63, d0 = tid >> 6;
        #pragma unroll
        for (int d = d0; d < 128; d += 4)
            xs[d * 64 + t] = xb[d * TT + t];
    }
    __syncthreads();

    const int tx = tid & 31;   // g chunks: tx*4 and 128+tx*4
    const int ty = tid >> 5;   // t chunks: ty*4 and 32+ty*4

    float acc[8][8];
    #pragma unroll
    for (int a = 0; a < 8; a++)
        #pragma unroll
        for (int e = 0; e < 8; e++) acc[a][e] = 0.0f;

    #pragma unroll 4
    for (int d = 0; d < 128; d++) {
        float4 xa = *(const float4*)&xs[d * 64 + ty * 4];
        float4 xb4 = *(const float4*)&xs[d * 64 + 32 + ty * 4];
        float4 wa = *(const float4*)&wt[d * 260 + tx * 4];
        float4 wb = *(const float4*)&wt[d * 260 + 128 + tx * 4];
        float xv[8] = {xa.x, xa.y, xa.z, xa.w, xb4.x, xb4.y, xb4.z, xb4.w};
        float wv[8] = {wa.x, wa.y, wa.z, wa.w, wb.x, wb.y, wb.z, wb.w};
        #pragma unroll
        for (int a = 0; a < 8; a++)
            #pragma unroll
            for (int e = 0; e < 8; e++)
                acc[a][e] += xv[a] * wv[e];
    }

    // bias (b_ih0 + b_hh0) for this thread's 8 g's
    const float4* bi4 = (const float4*)b_ih0;
    const float4* bh4 = (const float4*)b_hh0;
    float4 bia = bi4[tx],      bha = bh4[tx];
    float4 bib = bi4[32 + tx], bhb = bh4[32 + tx];
    float blo[4] = {bia.x + bha.x, bia.y + bha.y, bia.z + bha.z, bia.w + bha.w};
    float bhi[4] = {bib.x + bhb.x, bib.y + bhb.y, bib.z + bhb.z, bib.w + bhb.w};

    #pragma unroll
    for (int a = 0; a < 8; a++) {
        int t = (a < 4) ? (ty * 4 + a) : (32 + ty * 4 + (a - 4));
        float* row = g_xp0 + ((size_t)b * TT + t0 + t) * GG;
        float4 lo = make_float4(acc[a][0] + blo[0], acc[a][1] + blo[1],
                                acc[a][2] + blo[2], acc[a][3] + blo[3]);
        float4 hi = make_float4(acc[a][4] + bhi[0], acc[a][5] + bhi[1],
                                acc[a][6] + bhi[2], acc[a][7] + bhi[3]);
        *(float4*)(row + tx * 4)       = lo;
        *(float4*)(row + 128 + tx * 4) = hi;
    }
}

// ---------------------------------------------------------------------------
// Kernel 2: fused 2-layer LSTM recurrence + final linear head.
// Grid: 128 CTAs x 8 batch rows. Block: 256 threads (thread = one gate col).
// smem (floats): whh0t[64][256] | wih1t[64][256] | whh1t[64][256] |
//                gsm[256][12] | h0s[64][8] | h1s[64][8]   = 212992 bytes
// wfct[64][128] aliases whh0t after the time loop.
// ---------------------------------------------------------------------------
__device__ __forceinline__ void cell_update(const float* __restrict__ gsm,
                                            float* __restrict__ hs,
                                            int pb, int ph, float& c)
{
    float ig = gsm[(ph)       * 12 + pb];
    float fg = gsm[(64 + ph)  * 12 + pb];
    float gg = gsm[(128 + ph) * 12 + pb];
    float og = gsm[(192 + ph) * 12 + pb];
    float i = sigm(ig), f = sigm(fg), g = tanh_acc(gg), o = sigm(og);
    c = f * c + i * g;
    hs[ph * 8 + pb] = o * tanh_acc(c);
}

__global__ __launch_bounds__(256) void k_lstm(
    const float* __restrict__ w_hh0,
    const float* __restrict__ w_ih1,
    const float* __restrict__ b_ih1,
    const float* __restrict__ b_hh1,
    const float* __restrict__ w_hh1,
    const float* __restrict__ w_fc,
    const float* __restrict__ b_fc,
    float* __restrict__ out)
{
    extern __shared__ float sm[];
    float* whh0t = sm;            // [64][256]
    float* wih1t = sm + 16384;    // [64][256]
    float* whh1t = sm + 32768;    // [64][256]
    float* gsm   = sm + 49152;    // [256][12] (pad 12 avoids STS conflicts)
    float* h0s   = sm + 52224;    // [64][8]
    float* h1s   = sm + 52736;    // [64][8]
    float* wfct  = sm;            // alias of whh0t, [64][128], used post-loop

    const int tid = threadIdx.x;
    const int b0  = blockIdx.x * 8;

    // Transpose the three [256][64] weight matrices into [k][g] layout
    for (int i = tid; i < 256 * 64; i += 256) {
        int g = i >> 6, k = i & 63;
        whh0t[k * 256 + g] = w_hh0[i];
        wih1t[k * 256 + g] = w_ih1[i];
        whh1t[k * 256 + g] = w_hh1[i];
    }
    for (int i = tid; i < 512; i += 256) { h0s[i] = 0.0f; h1s[i] = 0.0f; }

    const float bias1 = b_ih1[tid] + b_hh1[tid];

    // Each thread owns 2 (b,h) cell pairs for the elementwise phases
    const int p0 = tid * 2;
    const int pb = p0 >> 6;        // same batch for both pairs (p0 even)
    const int ph = p0 & 63;        // hidden idx of pair 0; pair 1 is ph+1
    float c0a = 0.0f, c0b = 0.0f, c1a = 0.0f, c1b = 0.0f;

    __syncthreads();

    const float* xp = g_xp0 + (size_t)b0 * TT * GG + tid;

    for (int t = 0; t < TT; t++) {
        // ---- Phase A: gates0 = xp0[:, t, :] + h0 @ w_hh0^T ----
        float xv[8];
        #pragma unroll
        for (int b = 0; b < 8; b++)
            xv[b] = xp[((size_t)b * TT + t) * GG];

        float acc[8] = {0, 0, 0, 0, 0, 0, 0, 0};
        #pragma unroll 4
        for (int k = 0; k < 64; k++) {
            float w = whh0t[k * 256 + tid];
            float4 ha = *(const float4*)&h0s[k * 8];
            float4 hb = *(const float4*)&h0s[k * 8 + 4];
            acc[0] += w * ha.x; acc[1] += w * ha.y;
            acc[2] += w * ha.z; acc[3] += w * ha.w;
            acc[4] += w * hb.x; acc[5] += w * hb.y;
            acc[6] += w * hb.z; acc[7] += w * hb.w;
        }
        #pragma unroll
        for (int b = 0; b < 8; b++) gsm[tid * 12 + b] = acc[b] + xv[b];
        __syncthreads();

        // ---- Phase B: layer-0 cell update ----
        cell_update(gsm, h0s, pb, ph,     c0a);
        cell_update(gsm, h0s, pb, ph + 1, c0b);
        __syncthreads();

        // ---- Phase C: gates1 = bias1 + h0 @ w_ih1^T + h1 @ w_hh1^T ----
        float a1[8];
        #pragma unroll
        for (int b = 0; b < 8; b++) a1[b] = bias1;
        #pragma unroll 4
        for (int k = 0; k < 64; k++) {
            float w = wih1t[k * 256 + tid];
            float4 ha = *(const float4*)&h0s[k * 8];
            float4 hb = *(const float4*)&h0s[k * 8 + 4];
            a1[0] += w * ha.x; a1[1] += w * ha.y;
            a1[2] += w * ha.z; a1[3] += w * ha.w;
            a1[4] += w * hb.x; a1[5] += w * hb.y;
            a1[6] += w * hb.z; a1[7] += w * hb.w;
        }
        #pragma unroll 4
        for (int k = 0; k < 64; k++) {
            float w = whh1t[k * 256 + tid];
            float4 ha = *(const float4*)&h1s[k * 8];
            float4 hb = *(const float4*)&h1s[k * 8 + 4];
            a1[0] += w * ha.x; a1[1] += w * ha.y;
            a1[2] += w * ha.z; a1[3] += w * ha.w;
            a1[4] += w * hb.x; a1[5] += w * hb.y;
            a1[6] += w * hb.z; a1[7] += w * hb.w;
        }
        #pragma unroll
        for (int b = 0; b < 8; b++) gsm[tid * 12 + b] = a1[b];
        __syncthreads();

        // ---- Phase D: layer-1 cell update ----
        cell_update(gsm, h1s, pb, ph,     c1a);
        cell_update(gsm, h1s, pb, ph + 1, c1b);
        __syncthreads();
    }

    // ---- Head: scores[b, :] = hT @ w_fc^T + b_fc ----
    // Reuse whh0t region for wfct[k][o] (safe: loop fully synced above)
    for (int i = tid; i < 128 * 64; i += 256) {
        int o = i >> 6, k = i & 63;
        wfct[k * 128 + o] = w_fc[i];
    }
    __syncthreads();

    #pragma unroll
    for (int q = 0; q < 4; q++) {
        int p  = tid + q * 256;   // 0..1023
        int bo = p >> 7;          // batch row 0..7
        int o  = p & 127;         // output feature
        float acc = b_fc[o];
        #pragma unroll 4
        for (int k = 0; k < 64; k++)
            acc += h1s[k * 8 + bo] * wfct[k * 128 + o];
        out[(size_t)(b0 + bo) * 128 + o] = acc;
    }
}

// ---------------------------------------------------------------------------
// Launch
// ---------------------------------------------------------------------------
extern "C" void kernel_launch(void* const* d_in, const int* in_sizes, int n_in,
                              void* d_out, int out_size)
{
    const float* x     = (const float*)d_in[0];
    const float* w_ih0 = (const float*)d_in[1];
    const float* w_hh0 = (const float*)d_in[2];
    const float* b_ih0 = (const float*)d_in[3];
    const float* b_hh0 = (const float*)d_in[4];
    const float* w_ih1 = (const float*)d_in[5];
    const float* w_hh1 = (const float*)d_in[6];
    const float* b_ih1 = (const float*)d_in[7];
    const float* b_hh1 = (const float*)d_in[8];
    const float* w_fc  = (const float*)d_in[9];
    const float* b_fc  = (const float*)d_in[10];
    float* out = (float*)d_out;

    const int smem1 = (128 * 260 + 128 * 64) * 4;  // 165888
    const int smem2 = 53248 * 4;                   // 212992

    cudaFuncSetAttribute(k_inproj, cudaFuncAttributeMaxDynamicSharedMemorySize, smem1);
    cudaFuncSetAttribute(k_lstm,   cudaFuncAttributeMaxDynamicSharedMemorySize, smem2);

    k_inproj<<<4096, 256, smem1>>>(x, w_ih0, b_ih0, b_hh0);
    k_lstm<<<128, 256, smem2>>>(w_hh0, w_ih1, b_ih1, b_hh1, w_hh1, w_fc, b_fc, out);
}

// round 3
// speedup vs baseline: 1.2853x; 1.2853x over previous
#include <cuda_runtime.h>

#define BB 1024
#define DD 128
#define TT 256
#define HH 64
#define GG 256  // 4*H

typedef unsigned long long ull;

// 256 MB scratch for xp0 = xt @ w_ih0^T + (b_ih0 + b_hh0), layout [B][T][4H]
__device__ float g_xp0[(size_t)BB * TT * GG];

// ---------------------------------------------------------------------------
// f32x2 helpers (packed dual-FMA; ptxas never emits FFMA2 from C++)
// ---------------------------------------------------------------------------
__device__ __forceinline__ void ffma2(ull& d, ull a, ull b) {
    asm("fma.rn.f32x2 %0, %1, %2, %0;" : "+l"(d) : "l"(a), "l"(b));
}
__device__ __forceinline__ float2 u2f(ull u) {
    float2 r;
    r.x = __uint_as_float((unsigned)(u & 0xffffffffULL));
    r.y = __uint_as_float((unsigned)(u >> 32));
    return r;
}

// ---------------------------------------------------------------------------
// Activations
// ---------------------------------------------------------------------------
__device__ __forceinline__ float sigm(float x) {
    return __fdividef(1.0f, 1.0f + __expf(-x));
}
__device__ __forceinline__ float tanh_acc(float x) {
    float a = fabsf(x);
    float e = __expf(-2.0f * a);
    float r = (1.0f - e) * __fdividef(1.0f, 1.0f + e);
    return copysignf(r, x);
}

// ---------------------------------------------------------------------------
// Kernel 1: xp0[b, t, g] = sum_d x[b, d, t] * w_ih0[g, d] + bias[g]
// Grid: 1024 CTAs (one batch row each, 4 t-tiles of 64). Block: 256 threads.
// smem: wt[128][260] (transposed W) + xd[128][64] duplicated float2 = 198656 B
// f32x2: acc(t, g-pair); w naturally g-paired, x duplicated in smem (no MOVs).
// ---------------------------------------------------------------------------
__global__ __launch_bounds__(256) void k_inproj(
    const float* __restrict__ x,
    const float* __restrict__ w_ih0,
    const float* __restrict__ b_ih0,
    const float* __restrict__ b_hh0)
{
    extern __shared__ float sm[];
    float* wt = sm;              // [128][260]
    float* xd = sm + 128 * 260;  // [128][64] of float2 {v, v}

    const int tid = threadIdx.x;
    const int b   = blockIdx.x;

    // Load w_ih0 [256][128] -> wt[d][g] (transposed; one-time cost)
    {
        const float4* w4 = (const float4*)w_ih0;  // 8192 float4s
        #pragma unroll
        for (int i = 0; i < 32; i++) {
            int j  = tid + i * 256;
            int g  = j >> 5;
            int dq = j & 31;
            float4 v = w4[j];
            wt[(4 * dq + 0) * 260 + g] = v.x;
            wt[(4 * dq + 1) * 260 + g] = v.y;
            wt[(4 * dq + 2) * 260 + g] = v.z;
            wt[(4 * dq + 3) * 260 + g] = v.w;
        }
    }

    const int tx = tid & 31;   // g chunks: tx*4 and 128+tx*4
    const int ty = tid >> 5;   // t chunks: ty*4 and 32+ty*4

    // bias (b_ih0 + b_hh0) for this thread's 8 g's
    const float4* bi4 = (const float4*)b_ih0;
    const float4* bh4 = (const float4*)b_hh0;
    float4 bia = bi4[tx],      bha = bh4[tx];
    float4 bib = bi4[32 + tx], bhb = bh4[32 + tx];
    float blo[4] = {bia.x + bha.x, bia.y + bha.y, bia.z + bha.z, bia.w + bha.w};
    float bhi[4] = {bib.x + bhb.x, bib.y + bhb.y, bib.z + bhb.z, bib.w + bhb.w};

    for (int tt = 0; tt < 4; tt++) {
        const int t0 = tt * 64;
        __syncthreads();  // protect xd (and wt on first iter) before rewrite

        // Load x tile duplicated: xd2[d][t] = {x, x}
        {
            const float* xb = x + (size_t)b * DD * TT + t0;
            int t = tid & 63, d0 = tid >> 6;
            #pragma unroll
            for (int d = d0; d < 128; d += 4) {
                float v = xb[d * TT + t];
                ((float2*)xd)[d * 64 + t] = make_float2(v, v);
            }
        }
        __syncthreads();

        ull acc[8][4];
        #pragma unroll
        for (int a = 0; a < 8; a++)
            #pragma unroll
            for (int e = 0; e < 4; e++) acc[a][e] = 0ULL;

        #pragma unroll 4
        for (int d = 0; d < 128; d++) {
            // 4 LDS.128: x dups for 8 t (broadcast within warp)
            ulonglong2 x01 = *(const ulonglong2*)&xd[(d * 64 + ty * 4) * 2];
            ulonglong2 x23 = *(const ulonglong2*)&xd[(d * 64 + ty * 4 + 2) * 2];
            ulonglong2 x45 = *(const ulonglong2*)&xd[(d * 64 + 32 + ty * 4) * 2];
            ulonglong2 x67 = *(const ulonglong2*)&xd[(d * 64 + 32 + ty * 4 + 2) * 2];
            // 2 LDS.128: w for 8 g = 4 natural g-pairs
            ulonglong2 wa = *(const ulonglong2*)&wt[d * 260 + tx * 4];
            ulonglong2 wb = *(const ulonglong2*)&wt[d * 260 + 128 + tx * 4];
            ull xv[8] = {x01.x, x01.y, x23.x, x23.y, x45.x, x45.y, x67.x, x67.y};
            ull wp[4] = {wa.x, wa.y, wb.x, wb.y};
            #pragma unroll
            for (int a = 0; a < 8; a++)
                #pragma unroll
                for (int e = 0; e < 4; e++)
                    ffma2(acc[a][e], xv[a], wp[e]);
        }

        #pragma unroll
        for (int a = 0; a < 8; a++) {
            int t = (a < 4) ? (ty * 4 + a) : (32 + ty * 4 + (a - 4));
            float* row = g_xp0 + ((size_t)b * TT + t0 + t) * GG;
            float2 p0 = u2f(acc[a][0]), p1 = u2f(acc[a][1]);
            float2 p2 = u2f(acc[a][2]), p3 = u2f(acc[a][3]);
            float4 lo = make_float4(p0.x + blo[0], p0.y + blo[1],
                                    p1.x + blo[2], p1.y + blo[3]);
            float4 hi = make_float4(p2.x + bhi[0], p2.y + bhi[1],
                                    p3.x + bhi[2], p3.y + bhi[3]);
            *(float4*)(row + tx * 4)       = lo;
            *(float4*)(row + 128 + tx * 4) = hi;
        }
    }
}

// ---------------------------------------------------------------------------
// Kernel 2: fused 2-layer LSTM recurrence + head. 128 CTAs x 8 batch rows.
// 256 threads; thread = gate column g = tid, 8 batch rows.
// f32x2 packing over k: acc halves = even/odd-k partial sums, recombined once.
// smem floats: w0q[16][256][4] | w1q | w2q | h0f[8][64] | h1f[8][64] |
//              gsm[256][9]   -> 209920 bytes
// ---------------------------------------------------------------------------
#define W0OFF 0
#define W1OFF 16384
#define W2OFF 32768
#define H0OFF 49152
#define H1OFF 49664
#define GSOFF 50176
#define SMFL  52480

__global__ __launch_bounds__(256) void k_lstm(
    const float* __restrict__ w_hh0,
    const float* __restrict__ w_ih1,
    const float* __restrict__ b_ih1,
    const float* __restrict__ b_hh1,
    const float* __restrict__ w_hh1,
    const float* __restrict__ w_fc,
    const float* __restrict__ b_fc,
    float* __restrict__ out)
{
    extern __shared__ float sm[];
    float* w0q = sm + W0OFF;
    float* w1q = sm + W1OFF;
    float* w2q = sm + W2OFF;
    float* h0f = sm + H0OFF;
    float* h1f = sm + H1OFF;
    float* gsm = sm + GSOFF;

    const int tid = threadIdx.x;
    const int b0  = blockIdx.x * 8;

    // Repack [256][64] weights -> [k4][g] float4 (k-grouped for f32x2 pairs)
    {
        const float4* a4 = (const float4*)w_hh0;
        const float4* b4 = (const float4*)w_ih1;
        const float4* c4 = (const float4*)w_hh1;
        #pragma unroll
        for (int i = 0; i < 16; i++) {
            int j  = tid + i * 256;        // 0..4095
            int g  = j >> 4;
            int k4 = j & 15;
            ((float4*)w0q)[k4 * 256 + g] = a4[j];
            ((float4*)w1q)[k4 * 256 + g] = b4[j];
            ((float4*)w2q)[k4 * 256 + g] = c4[j];
        }
    }
    for (int i = tid; i < 512; i += 256) { h0f[i] = 0.0f; h1f[i] = 0.0f; }

    const float bias1 = b_ih1[tid] + b_hh1[tid];

    // Cell ownership: (h, cb) and (h, cb+4), h = tid&63, cb = tid>>6
    const int ch = tid & 63;
    const int cb = tid >> 6;
    float c0a = 0.0f, c0b = 0.0f, c1a = 0.0f, c1b = 0.0f;

    __syncthreads();

    const float* xp = g_xp0 + (size_t)b0 * TT * GG + tid;

    // Prefetch xp for t=0
    float xv[8];
    #pragma unroll
    for (int b = 0; b < 8; b++) xv[b] = xp[((size_t)b * TT) * GG];

    for (int t = 0; t < TT; t++) {
        // ---- Phase A: gates0 = xp0[:, t, :] + h0 @ w_hh0^T ----
        ull acc[8];
        #pragma unroll
        for (int b = 0; b < 8; b++) acc[b] = 0ULL;

        #pragma unroll
        for (int k4 = 0; k4 < 16; k4++) {
            ulonglong2 w = *(const ulonglong2*)&w0q[k4 * 1024 + tid * 4];
            #pragma unroll
            for (int b = 0; b < 8; b++) {
                ulonglong2 h = *(const ulonglong2*)&h0f[b * 64 + k4 * 4];
                ffma2(acc[b], w.x, h.x);
                ffma2(acc[b], w.y, h.y);
            }
        }
        #pragma unroll
        for (int b = 0; b < 8; b++) {
            float2 p = u2f(acc[b]);
            gsm[tid * 9 + b] = xv[b] + p.x + p.y;
        }
        __syncthreads();  // (1)

        // ---- layer-0 cell updates (2 per thread) ----
        {
            float i0 = gsm[ch * 9 + cb],        f0 = gsm[(64 + ch) * 9 + cb];
            float g0 = gsm[(128 + ch) * 9 + cb], o0 = gsm[(192 + ch) * 9 + cb];
            float i1 = gsm[ch * 9 + cb + 4],        f1 = gsm[(64 + ch) * 9 + cb + 4];
            float g1 = gsm[(128 + ch) * 9 + cb + 4], o1 = gsm[(192 + ch) * 9 + cb + 4];
            c0a = sigm(f0) * c0a + sigm(i0) * tanh_acc(g0);
            c0b = sigm(f1) * c0b + sigm(i1) * tanh_acc(g1);
            h0f[cb * 64 + ch]       = sigm(o0) * tanh_acc(c0a);
            h0f[(cb + 4) * 64 + ch] = sigm(o1) * tanh_acc(c0b);
        }
        __syncthreads();  // (2)

        // Prefetch xp for next t (hidden under phase C)
        {
            int tn = (t + 1 < TT) ? t + 1 : TT - 1;
            #pragma unroll
            for (int b = 0; b < 8; b++)
                xv[b] = xp[((size_t)b * TT + tn) * GG];
        }

        // ---- Phase C: gates1 = bias1 + h0 @ w_ih1^T + h1 @ w_hh1^T ----
        #pragma unroll
        for (int b = 0; b < 8; b++) acc[b] = 0ULL;

        #pragma unroll
        for (int k4 = 0; k4 < 16; k4++) {
            ulonglong2 wa = *(const ulonglong2*)&w1q[k4 * 1024 + tid * 4];
            ulonglong2 wb = *(const ulonglong2*)&w2q[k4 * 1024 + tid * 4];
            #pragma unroll
            for (int b = 0; b < 8; b++) {
                ulonglong2 ha = *(const ulonglong2*)&h0f[b * 64 + k4 * 4];
                ulonglong2 hb = *(const ulonglong2*)&h1f[b * 64 + k4 * 4];
                ffma2(acc[b], wa.x, ha.x);
                ffma2(acc[b], wa.y, ha.y);
                ffma2(acc[b], wb.x, hb.x);
                ffma2(acc[b], wb.y, hb.y);
            }
        }
        #pragma unroll
        for (int b = 0; b < 8; b++) {
            float2 p = u2f(acc[b]);
            gsm[tid * 9 + b] = bias1 + p.x + p.y;
        }
        __syncthreads();  // (3)

        // ---- layer-1 cell updates ----
        {
            float i0 = gsm[ch * 9 + cb],        f0 = gsm[(64 + ch) * 9 + cb];
            float g0 = gsm[(128 + ch) * 9 + cb], o0 = gsm[(192 + ch) * 9 + cb];
            float i1 = gsm[ch * 9 + cb + 4],        f1 = gsm[(64 + ch) * 9 + cb + 4];
            float g1 = gsm[(128 + ch) * 9 + cb + 4], o1 = gsm[(192 + ch) * 9 + cb + 4];
            c1a = sigm(f0) * c1a + sigm(i0) * tanh_acc(g0);
            c1b = sigm(f1) * c1b + sigm(i1) * tanh_acc(g1);
            h1f[cb * 64 + ch]       = sigm(o0) * tanh_acc(c1a);
            h1f[(cb + 4) * 64 + ch] = sigm(o1) * tanh_acc(c1b);
        }
        __syncthreads();  // (4)
    }

    // ---- Head: scores[b, :] = hT @ w_fc^T + b_fc ----
    float* wfct = w0q;  // reuse (fully synced above): [k][o], 64x128
    for (int i = tid; i < 128 * 64; i += 256) {
        int o = i >> 6, k = i & 63;
        wfct[k * 128 + o] = w_fc[i];
    }
    __syncthreads();

    #pragma unroll
    for (int q = 0; q < 4; q++) {
        int p  = tid + q * 256;   // 0..1023
        int bo = p >> 7;          // batch row 0..7
        int o  = p & 127;         // output feature
        float acc = b_fc[o];
        #pragma unroll 4
        for (int k = 0; k < 64; k++)
            acc += h1f[bo * 64 + k] * wfct[k * 128 + o];
        out[(size_t)(b0 + bo) * 128 + o] = acc;
    }
}

// ---------------------------------------------------------------------------
// Launch
// ---------------------------------------------------------------------------
extern "C" void kernel_launch(void* const* d_in, const int* in_sizes, int n_in,
                              void* d_out, int out_size)
{
    const float* x     = (const float*)d_in[0];
    const float* w_ih0 = (const float*)d_in[1];
    const float* w_hh0 = (const float*)d_in[2];
    const float* b_ih0 = (const float*)d_in[3];
    const float* b_hh0 = (const float*)d_in[4];
    const float* w_ih1 = (const float*)d_in[5];
    const float* w_hh1 = (const float*)d_in[6];
    const float* b_ih1 = (const float*)d_in[7];
    const float* b_hh1 = (const float*)d_in[8];
    const float* w_fc  = (const float*)d_in[9];
    const float* b_fc  = (const float*)d_in[10];
    float* out = (float*)d_out;

    const int smem1 = (128 * 260 + 128 * 64 * 2) * 4;  // 198656
    const int smem2 = SMFL * 4;                        // 209920

    cudaFuncSetAttribute(k_inproj, cudaFuncAttributeMaxDynamicSharedMemorySize, smem1);
    cudaFuncSetAttribute(k_lstm,   cudaFuncAttributeMaxDynamicSharedMemorySize, smem2);

    k_inproj<<<1024, 256, smem1>>>(x, w_ih0, b_ih0, b_hh0);
    k_lstm<<<128, 256, smem2>>>(w_hh0, w_ih1, b_ih1, b_hh1, w_hh1, w_fc, b_fc, out);
}